// round 16
// baseline (speedup 1.0000x reference)
#include <cuda_runtime.h>
#include <cuda_fp16.h>
#include <cstdint>
#include <cstddef>

// ---------------- problem constants ----------------
#define Bb   16
#define Ss   512
#define Ll   12
#define Hh   12
#define DHh  64
#define Dd   768
#define Mm   13
#define PH   144
#define GM   8192
#define GK   9216
#define GN   768

// ---------------- GEMM tiling (R4 proven config) ----------------
#define BM   128
#define BN   128
#define BK   64
#define KIT  (GK / BK)           // 144
#define STAGES 3
#define LDA_H 72
#define LDB_H 136
#define SA_BYTES (BM * LDA_H * 2)         // 18432
#define SB_BYTES (BK * LDB_H * 2)         // 17408
#define STAGE_BYTES (SA_BYTES + SB_BYTES) // 35840
#define GEMM_DSMEM (STAGES * STAGE_BYTES) // 107520 -> 2 CTAs/SM

// mlp tail-work chunking
#define CH_ROWS 8
#define NCHUNK  (GM / CH_ROWS)   // 1024
#define D4      (Dd / 4)         // 192
#define NYT     (GM / BM)        // 64 M-row tiles

__device__ __half g_Ah[(size_t)GM * GK];     // mask-scaled fp16 A
__device__ __half g_Wh[(size_t)GK * GN];     // fp16 W_O (row-major [K][N])
__device__ float  g_bias[Bb * Dd];
__device__ float  g_mlpout[(size_t)GM * GN]; // fallback scratch
__device__ int    g_cnt;                     // tail work counter
__device__ int    g_done[NYT];               // per-M-tile epilogue completion (0..6)
__device__ int    g_flag[NCHUNK];            // 1 = chunk committed directly to out

// ============================ PTX helpers ============================
__device__ __forceinline__ uint32_t smem_u32(const void* p) {
    uint32_t a;
    asm("{ .reg .u64 t; cvta.to.shared.u64 t, %1; cvt.u32.u64 %0, t; }"
        : "=r"(a) : "l"(p));
    return a;
}
__device__ __forceinline__ void cpasync16(uint32_t dst, const void* src) {
    asm volatile("cp.async.cg.shared.global [%0], [%1], 16;"
                 :: "r"(dst), "l"(src));
}
__device__ __forceinline__ void cp_commit() {
    asm volatile("cp.async.commit_group;");
}
__device__ __forceinline__ void cp_wait1() {
    asm volatile("cp.async.wait_group 1;");
}
__device__ __forceinline__ void ldsm4(uint32_t* r, uint32_t addr) {
    asm volatile("ldmatrix.sync.aligned.m8n8.x4.shared.b16 {%0,%1,%2,%3}, [%4];"
                 : "=r"(r[0]), "=r"(r[1]), "=r"(r[2]), "=r"(r[3]) : "r"(addr));
}
__device__ __forceinline__ void ldsm4t(uint32_t* r, uint32_t addr) {
    asm volatile("ldmatrix.sync.aligned.m8n8.x4.trans.shared.b16 {%0,%1,%2,%3}, [%4];"
                 : "=r"(r[0]), "=r"(r[1]), "=r"(r[2]), "=r"(r[3]) : "r"(addr));
}
__device__ __forceinline__ void mma16816(float* c, const uint32_t* a,
                                         uint32_t b0, uint32_t b1) {
    asm volatile(
        "mma.sync.aligned.m16n8k16.row.col.f32.f16.f16.f32 "
        "{%0,%1,%2,%3}, {%4,%5,%6,%7}, {%8,%9}, {%0,%1,%2,%3};"
        : "+f"(c[0]), "+f"(c[1]), "+f"(c[2]), "+f"(c[3])
        : "r"(a[0]), "r"(a[1]), "r"(a[2]), "r"(a[3]), "r"(b0), "r"(b1));
}

// ============================ Kernel 1: bias (+ counter/flag reset) ============================
// grid (16, 6), 128 threads. 96 blocks x 128 = 12288 threads cover resets.
__global__ void __launch_bounds__(128)
bias_kernel(const float* __restrict__ mlp_mask,
            const float* __restrict__ attn_mask,
            const float* __restrict__ modal_mlp,
            const float* __restrict__ modal_attention,
            const float* __restrict__ post_bias) {
    int gid = (blockIdx.y * Bb + blockIdx.x) * 128 + threadIdx.x;
    if (gid == 0) g_cnt = 0;
    if (gid < NYT) g_done[gid] = 0;
    if (gid < NCHUNK) g_flag[gid] = 0;

    int b = blockIdx.x;
    int d = blockIdx.y * 128 + threadIdx.x;
    float acc = 0.f;
#pragma unroll
    for (int m = 0; m < Mm; m++)
        acc += (1.f - mlp_mask[b * Mm + m]) * modal_mlp[m * Dd + d];
#pragma unroll 4
    for (int ph = 0; ph < PH; ph++)
        acc += (1.f - attn_mask[b * PH + ph]) * modal_attention[ph * Dd + d];
#pragma unroll
    for (int p = 0; p < Ll; p++)
        acc += post_bias[p * Dd + d];
    g_bias[b * Dd + d] = acc;
}

// ============================ Kernel 2: W_O -> fp16 ============================
__global__ void __launch_bounds__(256)
prep_w(const float* __restrict__ Wo) {
    size_t i = (size_t)blockIdx.x * 256 + threadIdx.x;
    float4 v = reinterpret_cast<const float4*>(Wo)[i];
    __half2* dst = reinterpret_cast<__half2*>(g_Wh);
    dst[i * 2]     = __floats2half2_rn(v.x, v.y);
    dst[i * 2 + 1] = __floats2half2_rn(v.z, v.w);
}

// ============================ Kernel 3: A mask-scale -> fp16 ============================
__global__ void __launch_bounds__(256)
prep_a(const float* __restrict__ attn_stack, const float* __restrict__ attn_mask) {
    __shared__ float sM[PH];
    int bs = blockIdx.x;
    int b  = bs >> 9;
    int t  = threadIdx.x;
    if (t < PH) sM[t] = attn_mask[b * PH + t];
    __syncthreads();
    const float4* src = reinterpret_cast<const float4*>(attn_stack + (size_t)bs * GK);
    __half2* dst = reinterpret_cast<__half2*>(g_Ah + (size_t)bs * GK);
#pragma unroll
    for (int i = 0; i < 9; i++) {
        int idx = t + 256 * i;
        float s = sM[idx >> 4];
        float4 v = src[idx];
        dst[idx * 2]     = __floats2half2_rn(v.x * s, v.y * s);
        dst[idx * 2 + 1] = __floats2half2_rn(v.z * s, v.w * s);
    }
}

// ============================ Kernel 4: GEMM + tail mlp (direct commit) ============================
// Phase 1: out[M,N] = g_Ah @ g_Wh (pure store; R4 mainloop untouched)
// Phase 2: CTAs work-steal 8-row mlp chunks; if the owning M-tile's 6 GEMM
//          CTAs have all stored, commit out += mlp directly; else stage to
//          g_mlpout for the cleanup pass. No spinning -> no deadlock.
__global__ void __launch_bounds__(256, 2)
attn_gemm(const float* __restrict__ mlp_stack,
          const float* __restrict__ mlp_mask,
          float* __restrict__ out) {
    extern __shared__ char smem[];
    __shared__ int sChunk;
    __shared__ int sSafe;
    const uint32_t s0 = smem_u32(smem);

    const int t    = threadIdx.x;
    const int lane = t & 31;
    const int wid  = t >> 5;
    const int wm   = wid >> 2;       // 0..1
    const int wn   = wid & 3;        // 0..3
    const int mRow0 = blockIdx.y * BM;
    const int nCol0 = blockIdx.x * BN;

    const __half* gA = g_Ah + (size_t)(mRow0 + (t >> 3)) * GK + (t & 7) * 8;
    const uint32_t sAw = s0 + (t >> 3) * (LDA_H * 2) + (t & 7) * 16;
    const __half* gB = g_Wh + (size_t)(t >> 4) * GN + nCol0 + (t & 15) * 8;
    const uint32_t sBw = s0 + SA_BYTES + (t >> 4) * (LDB_H * 2) + (t & 15) * 16;

    auto load_stage = [&](int kt, int st) {
        uint32_t so = st * STAGE_BYTES;
        const __half* ga = gA + kt * BK;
#pragma unroll
        for (int i = 0; i < 4; i++)
            cpasync16(sAw + so + i * 32 * (LDA_H * 2), ga + (size_t)i * 32 * GK);
        const __half* gb = gB + (size_t)kt * BK * GN;
#pragma unroll
        for (int i = 0; i < 4; i++)
            cpasync16(sBw + so + i * 16 * (LDB_H * 2), gb + (size_t)i * 16 * GN);
        cp_commit();
    };

    const uint32_t aBase = s0 + (wm * 64 + (lane & 15)) * (LDA_H * 2) + (lane >> 4) * 16;
    const uint32_t bBase = s0 + SA_BYTES + (lane & 15) * (LDB_H * 2) + wn * 64 + (lane >> 4) * 16;

    float acc[4][4][4];
#pragma unroll
    for (int mi = 0; mi < 4; mi++)
#pragma unroll
        for (int nt = 0; nt < 4; nt++)
#pragma unroll
            for (int r = 0; r < 4; r++) acc[mi][nt][r] = 0.f;

    load_stage(0, 0);
    load_stage(1, 1);

    int st_c = 0;
    int st_l = 2;
    for (int kt = 0; kt < KIT; kt++) {
        cp_wait1();
        __syncthreads();
        if (kt + 2 < KIT) load_stage(kt + 2, st_l);
        else cp_commit();

        const uint32_t so = st_c * STAGE_BYTES;
#pragma unroll
        for (int ks = 0; ks < 4; ks++) {
            uint32_t af[4][4];
#pragma unroll
            for (int mi = 0; mi < 4; mi++)
                ldsm4(af[mi], aBase + so + mi * 16 * (LDA_H * 2) + ks * 32);
            uint32_t bf[2][4];
#pragma unroll
            for (int nj = 0; nj < 2; nj++)
                ldsm4t(bf[nj], bBase + so + ks * 16 * (LDB_H * 2) + nj * 32);
#pragma unroll
            for (int mi = 0; mi < 4; mi++)
#pragma unroll
                for (int nt = 0; nt < 4; nt++)
                    mma16816(acc[mi][nt], af[mi],
                             bf[nt >> 1][(nt & 1) * 2], bf[nt >> 1][(nt & 1) * 2 + 1]);
        }
        st_c = (st_c == STAGES - 1) ? 0 : st_c + 1;
        st_l = (st_l == STAGES - 1) ? 0 : st_l + 1;
    }

    // ---- epilogue: pure store, then publish completion ----
    {
        const int g  = lane >> 2;
        const int tq = lane & 3;
#pragma unroll
        for (int mi = 0; mi < 4; mi++) {
            int row0 = mRow0 + wm * 64 + mi * 16 + g;
#pragma unroll
            for (int nt = 0; nt < 4; nt++) {
                int col = nCol0 + wn * 32 + nt * 8 + tq * 2;
                float2 v0, v1;
                v0.x = acc[mi][nt][0]; v0.y = acc[mi][nt][1];
                v1.x = acc[mi][nt][2]; v1.y = acc[mi][nt][3];
                *reinterpret_cast<float2*>(out + (size_t)row0 * GN + col)       = v0;
                *reinterpret_cast<float2*>(out + (size_t)(row0 + 8) * GN + col) = v1;
            }
        }
    }
    __threadfence();
    __syncthreads();
    if (t == 0) atomicAdd(&g_done[blockIdx.y], 1);

    // ---- phase 2: work-steal mlp chunks ----
    for (;;) {
        __syncthreads();
        if (t == 0) {
            sChunk = atomicAdd(&g_cnt, 1);
            if (sChunk < NCHUNK) {
                int y = (sChunk * CH_ROWS) >> 7;
                int dn = atomicAdd(&g_done[y], 0);
                __threadfence();
                sSafe = (dn == 6);
            }
        }
        __syncthreads();
        int c = sChunk;
        if (c >= NCHUNK) break;
        const bool direct = (sSafe != 0);

        int row0 = c * CH_ROWS;
        int b = row0 >> 9;
        float w[Mm];
#pragma unroll
        for (int m = 0; m < Mm; m++) w[m] = __ldg(&mlp_mask[b * Mm + m]);
        const float4* biasb = reinterpret_cast<const float4*>(g_bias) + b * D4;

#pragma unroll
        for (int i = 0; i < (CH_ROWS * D4) / 256; i++) {   // 6 iters
            int idx  = t + 256 * i;
            int r    = idx / D4;
            int col4 = idx - r * D4;
            const float4* mp = reinterpret_cast<const float4*>(mlp_stack) +
                               (size_t)(row0 + r) * Mm * D4 + col4;
            float4 acc4 = __ldg(biasb + col4);
#pragma unroll
            for (int m = 0; m < Mm; m++) {
                float4 v = __ldg(mp + m * D4);
                acc4.x += w[m] * v.x; acc4.y += w[m] * v.y;
                acc4.z += w[m] * v.z; acc4.w += w[m] * v.w;
            }
            size_t off = (size_t)(row0 + r) * D4 + col4;
            if (direct) {
                float4* o = reinterpret_cast<float4*>(out) + off;
                float4 cur = *o;
                cur.x += acc4.x; cur.y += acc4.y; cur.z += acc4.z; cur.w += acc4.w;
                *o = cur;
            } else {
                reinterpret_cast<float4*>(g_mlpout)[off] = acc4;
            }
        }
        if (direct && t == 0) g_flag[c] = 1;
    }
}

// ============================ Kernel 5: cleanup add (leftover chunks only) ============================
__global__ void __launch_bounds__(256)
cleanup_add(float* __restrict__ out) {
    int c = blockIdx.x;
    if (g_flag[c]) return;
    int row0 = c * CH_ROWS;
    int t = threadIdx.x;
#pragma unroll
    for (int i = 0; i < (CH_ROWS * D4) / 256; i++) {
        size_t off = (size_t)row0 * D4 + t + 256 * i;
        float4 a = reinterpret_cast<float4*>(out)[off];
        float4 bz = reinterpret_cast<const float4*>(g_mlpout)[off];
        a.x += bz.x; a.y += bz.y; a.z += bz.z; a.w += bz.w;
        reinterpret_cast<float4*>(out)[off] = a;
    }
}

// ============================ launch ============================
static const float* find_in(void* const* d_in, const int* in_sizes, int n_in,
                            long long want) {
    for (int i = 0; i < n_in; i++)
        if ((long long)in_sizes[i] == want) return (const float*)d_in[i];
    return nullptr;
}

extern "C" void kernel_launch(void* const* d_in, const int* in_sizes, int n_in,
                              void* d_out, int out_size) {
    const float* mlp_stack       = find_in(d_in, in_sizes, n_in, (long long)Bb * Ss * Mm * Dd);
    const float* attn_stack      = find_in(d_in, in_sizes, n_in, (long long)Bb * Ss * Ll * Hh * DHh);
    const float* mlp_mask        = find_in(d_in, in_sizes, n_in, (long long)Bb * Mm);
    const float* attn_mask       = find_in(d_in, in_sizes, n_in, (long long)Bb * Ll * Hh);
    const float* modal_mlp       = find_in(d_in, in_sizes, n_in, (long long)Mm * Dd);
    const float* modal_attention = find_in(d_in, in_sizes, n_in, (long long)Ll * Hh * Dd);
    const float* W_O             = find_in(d_in, in_sizes, n_in, (long long)Ll * Hh * DHh * Dd);
    const float* post_bias       = find_in(d_in, in_sizes, n_in, (long long)Ll * Dd);
    float* out = (float*)d_out;

    static bool inited = false;
    if (!inited) {
        cudaFuncSetAttribute(attn_gemm,
                             cudaFuncAttributeMaxDynamicSharedMemorySize, GEMM_DSMEM);
        inited = true;
    }

    // bias(+resets) -> prep_w -> prep_a -> gemm(+tail mlp, direct commit) -> cleanup
    bias_kernel<<<dim3(Bb, Dd / 128), 128>>>(mlp_mask, attn_mask, modal_mlp,
                                             modal_attention, post_bias);
    prep_w<<<(GK * GN / 4) / 256, 256>>>(W_O);
    prep_a<<<GM, 256>>>(attn_stack, attn_mask);
    dim3 ggrid(GN / BN, GM / BM);   // (6, 64)
    attn_gemm<<<ggrid, 256, GEMM_DSMEM>>>(mlp_stack, mlp_mask, out);
    cleanup_add<<<NCHUNK, 256>>>(out);
}

// round 17
// speedup vs baseline: 1.0290x; 1.0290x over previous
#include <cuda_runtime.h>
#include <cuda_fp16.h>
#include <cstdint>
#include <cstddef>

// ---------------- problem constants ----------------
#define Bb   16
#define Ss   512
#define Ll   12
#define Hh   12
#define DHh  64
#define Dd   768
#define Mm   13
#define PH   144
#define GM   8192
#define GK   9216
#define GN   768

// ---------------- GEMM tiling (R4 proven config) ----------------
#define BM   128
#define BN   128
#define BK   64
#define KIT  (GK / BK)           // 144
#define STAGES 3
#define LDA_H 72
#define LDB_H 136
#define SA_BYTES (BM * LDA_H * 2)         // 18432
#define SB_BYTES (BK * LDB_H * 2)         // 17408
#define STAGE_BYTES (SA_BYTES + SB_BYTES) // 35840
#define GEMM_DSMEM (STAGES * STAGE_BYTES) // 107520 -> 2 CTAs/SM

#define PA_BLOCKS 8192
#define PW_BLOCKS ((GK * GN / 4) / 256)   // 6912 float4-blocks of W
#define D4 (Dd / 4)

__device__ __half g_Ah[(size_t)GM * GK];     // mask-scaled fp16 A
__device__ __half g_Wh[(size_t)GK * GN];     // fp16 W_O (row-major [K][N])
__device__ float  g_bias[Bb * Dd];
__device__ float  g_mlpout[(size_t)GM * GN]; // mlp term + bias (scratch)

// ============================ PTX helpers ============================
__device__ __forceinline__ uint32_t smem_u32(const void* p) {
    uint32_t a;
    asm("{ .reg .u64 t; cvta.to.shared.u64 t, %1; cvt.u32.u64 %0, t; }"
        : "=r"(a) : "l"(p));
    return a;
}
__device__ __forceinline__ void cpasync16(uint32_t dst, const void* src) {
    asm volatile("cp.async.cg.shared.global [%0], [%1], 16;"
                 :: "r"(dst), "l"(src));
}
__device__ __forceinline__ void cp_commit() {
    asm volatile("cp.async.commit_group;");
}
__device__ __forceinline__ void cp_wait1() {
    asm volatile("cp.async.wait_group 1;");
}
__device__ __forceinline__ void ldsm4(uint32_t* r, uint32_t addr) {
    asm volatile("ldmatrix.sync.aligned.m8n8.x4.shared.b16 {%0,%1,%2,%3}, [%4];"
                 : "=r"(r[0]), "=r"(r[1]), "=r"(r[2]), "=r"(r[3]) : "r"(addr));
}
__device__ __forceinline__ void ldsm4t(uint32_t* r, uint32_t addr) {
    asm volatile("ldmatrix.sync.aligned.m8n8.x4.trans.shared.b16 {%0,%1,%2,%3}, [%4];"
                 : "=r"(r[0]), "=r"(r[1]), "=r"(r[2]), "=r"(r[3]) : "r"(addr));
}
__device__ __forceinline__ void mma16816(float* c, const uint32_t* a,
                                         uint32_t b0, uint32_t b1) {
    asm volatile(
        "mma.sync.aligned.m16n8k16.row.col.f32.f16.f16.f32 "
        "{%0,%1,%2,%3}, {%4,%5,%6,%7}, {%8,%9}, {%0,%1,%2,%3};"
        : "+f"(c[0]), "+f"(c[1]), "+f"(c[2]), "+f"(c[3])
        : "r"(a[0]), "r"(a[1]), "r"(a[2]), "r"(a[3]), "r"(b0), "r"(b1));
}

// ============================ Kernel 1: bias ============================
__global__ void __launch_bounds__(128)
bias_kernel(const float* __restrict__ mlp_mask,
            const float* __restrict__ attn_mask,
            const float* __restrict__ modal_mlp,
            const float* __restrict__ modal_attention,
            const float* __restrict__ post_bias) {
    int b = blockIdx.x;
    int d = blockIdx.y * 128 + threadIdx.x;
    float acc = 0.f;
#pragma unroll
    for (int m = 0; m < Mm; m++)
        acc += (1.f - mlp_mask[b * Mm + m]) * modal_mlp[m * Dd + d];
#pragma unroll 4
    for (int ph = 0; ph < PH; ph++)
        acc += (1.f - attn_mask[b * PH + ph]) * modal_attention[ph * Dd + d];
#pragma unroll
    for (int p = 0; p < Ll; p++)
        acc += post_bias[p * Dd + d];
    g_bias[b * Dd + d] = acc;
}

// ============================ Kernel 2: merged A + W prep (homogeneous streaming) ============================
// blocks [0, PA_BLOCKS): one (b,s) row of attn_stack -> mask-scaled fp16 g_Ah
// blocks [PA_BLOCKS, PA_BLOCKS+PW_BLOCKS): 256 float4 of W_O -> fp16 g_Wh
__global__ void __launch_bounds__(256)
prep_aw(const float* __restrict__ attn_stack,
        const float* __restrict__ attn_mask,
        const float* __restrict__ Wo) {
    const int blk = blockIdx.x;
    const int t   = threadIdx.x;
    if (blk < PA_BLOCKS) {
        __shared__ float sM[PH];
        int bs = blk;
        int b  = bs >> 9;
        if (t < PH) sM[t] = attn_mask[b * PH + t];
        __syncthreads();
        const float4* src = reinterpret_cast<const float4*>(attn_stack + (size_t)bs * GK);
        __half2* dst = reinterpret_cast<__half2*>(g_Ah + (size_t)bs * GK);
#pragma unroll
        for (int i = 0; i < 9; i++) {
            int idx = t + 256 * i;
            float s = sM[idx >> 4];
            float4 v = src[idx];
            dst[idx * 2]     = __floats2half2_rn(v.x * s, v.y * s);
            dst[idx * 2 + 1] = __floats2half2_rn(v.z * s, v.w * s);
        }
    } else {
        size_t i = (size_t)(blk - PA_BLOCKS) * 256 + t;
        float4 v = reinterpret_cast<const float4*>(Wo)[i];
        __half2* dst = reinterpret_cast<__half2*>(g_Wh);
        dst[i * 2]     = __floats2half2_rn(v.x, v.y);
        dst[i * 2 + 1] = __floats2half2_rn(v.z, v.w);
    }
}

// ============================ Kernel 3: mlp term -> scratch ============================
__global__ void __launch_bounds__(192)
mlp_kernel(const float* __restrict__ mlp_stack,
           const float* __restrict__ mlp_mask) {
    int bs = blockIdx.x;
    int b  = bs >> 9;
    int t  = threadIdx.x;
    const float4* mp =
        reinterpret_cast<const float4*>(mlp_stack) + (size_t)bs * Mm * D4;
    float4 acc = reinterpret_cast<const float4*>(g_bias)[b * D4 + t];
#pragma unroll
    for (int m = 0; m < Mm; m++) {
        float w  = __ldg(&mlp_mask[b * Mm + m]);
        float4 v = mp[m * D4 + t];
        acc.x += w * v.x; acc.y += w * v.y;
        acc.z += w * v.z; acc.w += w * v.w;
    }
    reinterpret_cast<float4*>(g_mlpout)[(size_t)bs * D4 + t] = acc;
}

// ============================ Kernel 4: fp16 mma.sync GEMM ============================
// out[M,N] = g_Ah[M,K] @ g_Wh[K,N] + g_mlpout[M,N]
// 256 threads = 8 warps (2x4), 64x32 warp tiles, 2 CTAs/SM. (R9 exact)
__global__ void __launch_bounds__(256, 2)
attn_gemm(float* __restrict__ out) {
    extern __shared__ char smem[];
    const uint32_t s0 = smem_u32(smem);

    const int t    = threadIdx.x;
    const int lane = t & 31;
    const int wid  = t >> 5;
    const int wm   = wid >> 2;       // 0..1
    const int wn   = wid & 3;        // 0..3
    const int mRow0 = blockIdx.y * BM;
    const int nCol0 = blockIdx.x * BN;

    const __half* gA = g_Ah + (size_t)(mRow0 + (t >> 3)) * GK + (t & 7) * 8;
    const uint32_t sAw = s0 + (t >> 3) * (LDA_H * 2) + (t & 7) * 16;
    const __half* gB = g_Wh + (size_t)(t >> 4) * GN + nCol0 + (t & 15) * 8;
    const uint32_t sBw = s0 + SA_BYTES + (t >> 4) * (LDB_H * 2) + (t & 15) * 16;

    auto load_stage = [&](int kt, int st) {
        uint32_t so = st * STAGE_BYTES;
        const __half* ga = gA + kt * BK;
#pragma unroll
        for (int i = 0; i < 4; i++)
            cpasync16(sAw + so + i * 32 * (LDA_H * 2), ga + (size_t)i * 32 * GK);
        const __half* gb = gB + (size_t)kt * BK * GN;
#pragma unroll
        for (int i = 0; i < 4; i++)
            cpasync16(sBw + so + i * 16 * (LDB_H * 2), gb + (size_t)i * 16 * GN);
        cp_commit();
    };

    const uint32_t aBase = s0 + (wm * 64 + (lane & 15)) * (LDA_H * 2) + (lane >> 4) * 16;
    const uint32_t bBase = s0 + SA_BYTES + (lane & 15) * (LDB_H * 2) + wn * 64 + (lane >> 4) * 16;

    float acc[4][4][4];
#pragma unroll
    for (int mi = 0; mi < 4; mi++)
#pragma unroll
        for (int nt = 0; nt < 4; nt++)
#pragma unroll
            for (int r = 0; r < 4; r++) acc[mi][nt][r] = 0.f;

    load_stage(0, 0);
    load_stage(1, 1);

    int st_c = 0;
    int st_l = 2;
    for (int kt = 0; kt < KIT; kt++) {
        cp_wait1();
        __syncthreads();
        if (kt + 2 < KIT) load_stage(kt + 2, st_l);
        else cp_commit();

        const uint32_t so = st_c * STAGE_BYTES;
#pragma unroll
        for (int ks = 0; ks < 4; ks++) {
            uint32_t af[4][4];
#pragma unroll
            for (int mi = 0; mi < 4; mi++)
                ldsm4(af[mi], aBase + so + mi * 16 * (LDA_H * 2) + ks * 32);
            uint32_t bf[2][4];
#pragma unroll
            for (int nj = 0; nj < 2; nj++)
                ldsm4t(bf[nj], bBase + so + ks * 16 * (LDB_H * 2) + nj * 32);
#pragma unroll
            for (int mi = 0; mi < 4; mi++)
#pragma unroll
                for (int nt = 0; nt < 4; nt++)
                    mma16816(acc[mi][nt], af[mi],
                             bf[nt >> 1][(nt & 1) * 2], bf[nt >> 1][(nt & 1) * 2 + 1]);
        }
        st_c = (st_c == STAGES - 1) ? 0 : st_c + 1;
        st_l = (st_l == STAGES - 1) ? 0 : st_l + 1;
    }

    // ---- epilogue: out = acc + mlpout ----
    const int g  = lane >> 2;
    const int tq = lane & 3;
#pragma unroll
    for (int mi = 0; mi < 4; mi++) {
        int row0 = mRow0 + wm * 64 + mi * 16 + g;
#pragma unroll
        for (int nt = 0; nt < 4; nt++) {
            int col = nCol0 + wn * 32 + nt * 8 + tq * 2;
            float2 u0 = *reinterpret_cast<const float2*>(g_mlpout + (size_t)row0 * GN + col);
            float2 u1 = *reinterpret_cast<const float2*>(g_mlpout + (size_t)(row0 + 8) * GN + col);
            float2 v0, v1;
            v0.x = acc[mi][nt][0] + u0.x; v0.y = acc[mi][nt][1] + u0.y;
            v1.x = acc[mi][nt][2] + u1.x; v1.y = acc[mi][nt][3] + u1.y;
            *reinterpret_cast<float2*>(out + (size_t)row0 * GN + col)       = v0;
            *reinterpret_cast<float2*>(out + (size_t)(row0 + 8) * GN + col) = v1;
        }
    }
}

// ============================ launch ============================
static const float* find_in(void* const* d_in, const int* in_sizes, int n_in,
                            long long want) {
    for (int i = 0; i < n_in; i++)
        if ((long long)in_sizes[i] == want) return (const float*)d_in[i];
    return nullptr;
}

extern "C" void kernel_launch(void* const* d_in, const int* in_sizes, int n_in,
                              void* d_out, int out_size) {
    const float* mlp_stack       = find_in(d_in, in_sizes, n_in, (long long)Bb * Ss * Mm * Dd);
    const float* attn_stack      = find_in(d_in, in_sizes, n_in, (long long)Bb * Ss * Ll * Hh * DHh);
    const float* mlp_mask        = find_in(d_in, in_sizes, n_in, (long long)Bb * Mm);
    const float* attn_mask       = find_in(d_in, in_sizes, n_in, (long long)Bb * Ll * Hh);
    const float* modal_mlp       = find_in(d_in, in_sizes, n_in, (long long)Mm * Dd);
    const float* modal_attention = find_in(d_in, in_sizes, n_in, (long long)Ll * Hh * Dd);
    const float* W_O             = find_in(d_in, in_sizes, n_in, (long long)Ll * Hh * DHh * Dd);
    const float* post_bias       = find_in(d_in, in_sizes, n_in, (long long)Ll * Dd);
    float* out = (float*)d_out;

    static cudaStream_t s2 = nullptr;
    static cudaEvent_t evFork = nullptr, evJoin = nullptr;
    static bool inited = false;
    if (!inited) {
        cudaFuncSetAttribute(attn_gemm,
                             cudaFuncAttributeMaxDynamicSharedMemorySize, GEMM_DSMEM);
        cudaStreamCreateWithFlags(&s2, cudaStreamNonBlocking);
        cudaEventCreateWithFlags(&evFork, cudaEventDisableTiming);
        cudaEventCreateWithFlags(&evJoin, cudaEventDisableTiming);
        inited = true;
    }

    // main: bias -> (fork) -> prep_aw -> (join) -> gemm(+mlpout)
    bias_kernel<<<dim3(Bb, Dd / 128), 128>>>(mlp_mask, attn_mask, modal_mlp,
                                             modal_attention, post_bias);
    cudaEventRecord(evFork, 0);
    cudaStreamWaitEvent(s2, evFork, 0);

    // side: mlp term into scratch (overlaps merged prep)
    mlp_kernel<<<GM, D4, 0, s2>>>(mlp_stack, mlp_mask);
    cudaEventRecord(evJoin, s2);

    prep_aw<<<PA_BLOCKS + PW_BLOCKS, 256>>>(attn_stack, attn_mask, W_O);

    cudaStreamWaitEvent(0, evJoin, 0);
    dim3 ggrid(GN / BN, GM / BM);   // (6, 64)
    attn_gemm<<<ggrid, 256, GEMM_DSMEM>>>(out);
}